// round 1
// baseline (speedup 1.0000x reference)
#include <cuda_runtime.h>
#include <cstdint>
#include <cstddef>

// Problem constants
#define NN   50000
#define EE   200000
#define RR   4
#define DIN  128
#define DH   128
#define DOUT 64

// -------- scratch (static device globals; no runtime allocation) --------
__device__ float g_Wh1[RR * NN * DH];       // 102.4 MB  per-etype L1 GEMM out
__device__ float g_h[NN * DH];              //  25.6 MB  L1 aggregate -> h
__device__ float g_Wh2[RR * NN * DOUT];     //  51.2 MB  per-etype L2 GEMM out
__device__ float g_featT[DIN * NN];         //  25.6 MB  feat transposed (k-major)
__device__ float g_hT[DH * NN];             //  25.6 MB  relu(h) transposed
__device__ float g_dinv[RR * NN];           //  1/deg (0 if deg==0)
__device__ int   g_deg[RR * NN];

// -------- packed f32x2 FMA (ptxas never auto-emits FFMA2; 2x fp32 rate) ----
static __device__ __forceinline__ void fma2(unsigned long long& d,
                                            unsigned long long a,
                                            unsigned long long b) {
    asm("fma.rn.f32x2 %0, %1, %2, %0;" : "+l"(d) : "l"(a), "l"(b));
}

// ---------------- degree / init kernels ----------------
__global__ void k_zero_deg() {
    int i = blockIdx.x * 256 + threadIdx.x;
    if (i < RR * NN) g_deg[i] = 0;
}

__global__ void k_count(const int* __restrict__ edges) {
    int i = blockIdx.x * 256 + threadIdx.x;
    if (i >= RR * EE) return;
    int r = i / EE;
    int e = i - r * EE;
    int dst = edges[r * 2 * EE + EE + e];
    atomicAdd(&g_deg[r * NN + dst], 1);
}

__global__ void k_dinv() {
    int i = blockIdx.x * 256 + threadIdx.x;
    if (i >= RR * NN) return;
    int d = g_deg[i];
    g_dinv[i] = (d > 0) ? (1.0f / (float)d) : 0.0f;
}

// h accumulator init = sum_r (deg_r>0 ? b1_r : 0)   (mean of const bias = bias)
__global__ void k_init_h(const float* __restrict__ b1) {
    int i = blockIdx.x * 256 + threadIdx.x;
    if (i >= NN * DH) return;
    int n = i >> 7, c = i & 127;
    float s = 0.f;
#pragma unroll
    for (int r = 0; r < RR; ++r)
        if (g_deg[r * NN + n] > 0) s += b1[r * DH + c];
    g_h[i] = s;
}

__global__ void k_init_out(const float* __restrict__ b2, float* __restrict__ out) {
    int i = blockIdx.x * 256 + threadIdx.x;
    if (i >= NN * DOUT) return;
    int n = i >> 6, c = i & 63;
    float s = 0.f;
#pragma unroll
    for (int r = 0; r < RR; ++r)
        if (g_deg[r * NN + n] > 0) s += b2[r * DOUT + c];
    out[i] = s;
}

// ---------------- transpose [NN][128] -> [128][NN] (opt. fused relu) ------
template <bool RELU>
__global__ void k_transpose(const float* __restrict__ in, float* __restrict__ out) {
    __shared__ float tile[32][33];
    const int n0 = blockIdx.x * 32;
    const int c0 = blockIdx.y * 32;
    const int tx = threadIdx.x, ty = threadIdx.y;
#pragma unroll
    for (int i = 0; i < 32; i += 8) {
        const int n = n0 + ty + i;
        float v = 0.f;
        if (n < NN) v = in[(size_t)n * 128 + c0 + tx];
        if (RELU) v = fmaxf(v, 0.f);
        tile[ty + i][tx] = v;
    }
    __syncthreads();
    const int n = n0 + tx;
    if (n < NN) {
#pragma unroll
        for (int i = 0; i < 32; i += 8)
            out[(size_t)(c0 + ty + i) * NN + n] = tile[tx][ty + i];
    }
}

// ---------------- batched SGEMM: C[r] = A @ W[r] (no bias) ----------------
// A given k-major (transposed) so both smem operands are k-major ->
// conflict-free vector LDS. W stored duplicated so each n-column is a packed
// {w,w} f32x2 operand; A pairs (m,m+1) are naturally contiguous in k-major.
// Tile 128(m) x NCOLS(n) x 128(k), 256 threads, each thread 8m x TN n.
template <int NCOLS, int LOGN>
__global__ __launch_bounds__(256, 1)
void k_gemm(const float* __restrict__ AT,     // [128][NN] k-major
            const float* __restrict__ Wall,   // [RR][128][NCOLS]
            float* __restrict__ Call)         // [RR][NN][NCOLS]
{
    constexpr int TN = NCOLS / 16;
    extern __shared__ __align__(16) float smem[];
    float* As = smem;               // [128][128]  (k-major)
    float* Bs = smem + 128 * 128;   // [128][2*NCOLS] duplicated

    const int r  = blockIdx.z;
    const int m0 = blockIdx.x * 128;
    const float* W = Wall + r * 128 * NCOLS;
    float* C = Call + (size_t)r * NN * NCOLS;

    const int tid = threadIdx.x;
    {   // A tile: warp w loads rows k=w*16..+15, lanes do float4 along m
        const int w = tid >> 5, l = tid & 31;
        const int m = 4 * l;
        const int gm = m0 + m;  // NN % 4 == 0 so whole-float4 guard is exact
#pragma unroll
        for (int it = 0; it < 16; ++it) {
            const int k = w * 16 + it;
            float4 v = make_float4(0.f, 0.f, 0.f, 0.f);
            if (gm < NN) v = *reinterpret_cast<const float4*>(AT + (size_t)k * NN + gm);
            *reinterpret_cast<float4*>(As + k * 128 + m) = v;
        }
    }
    {   // W tile, duplicated: Bs[k][2n]=Bs[k][2n+1]=W[k][n]
#pragma unroll
        for (int idx = tid; idx < 128 * NCOLS; idx += 256) {
            const int k = idx >> LOGN;
            const int n = idx & (NCOLS - 1);
            const float wv = W[idx];
            *reinterpret_cast<float2*>(Bs + k * 2 * NCOLS + 2 * n) = make_float2(wv, wv);
        }
    }
    __syncthreads();

    const int tx = tid & 15;   // n group
    const int ty = tid >> 4;   // m group (8 rows = 4 pairs)

    unsigned long long acc[4][TN];
#pragma unroll
    for (int p = 0; p < 4; ++p)
#pragma unroll
        for (int j = 0; j < TN; ++j) acc[p][j] = 0ull;

#pragma unroll 8
    for (int k = 0; k < 128; ++k) {
        unsigned long long a[4], b[TN];
        ulonglong2 av0 = *reinterpret_cast<const ulonglong2*>(As + k * 128 + ty * 8);
        ulonglong2 av1 = *reinterpret_cast<const ulonglong2*>(As + k * 128 + ty * 8 + 4);
        a[0] = av0.x; a[1] = av0.y; a[2] = av1.x; a[3] = av1.y;
#pragma unroll
        for (int q = 0; q < TN / 2; ++q) {
            ulonglong2 bv = *reinterpret_cast<const ulonglong2*>(
                Bs + k * 2 * NCOLS + tx * 2 * TN + 4 * q);
            b[2 * q] = bv.x; b[2 * q + 1] = bv.y;
        }
#pragma unroll
        for (int p = 0; p < 4; ++p)
#pragma unroll
            for (int j = 0; j < TN; ++j)
                fma2(acc[p][j], a[p], b[j]);
    }

    // epilogue: acc[p][j] = {C[2p][n0+j], C[2p+1][n0+j]}
#pragma unroll
    for (int p = 0; p < 4; ++p) {
        float lo[TN], hi[TN];
#pragma unroll
        for (int j = 0; j < TN; ++j) {
            float2 t = *reinterpret_cast<float2*>(&acc[p][j]);
            lo[j] = t.x; hi[j] = t.y;
        }
        const int row0 = m0 + ty * 8 + 2 * p;
        if (row0 < NN) {
            float* cp = C + (size_t)row0 * NCOLS + tx * TN;
#pragma unroll
            for (int v = 0; v < TN / 4; ++v)
                *reinterpret_cast<float4*>(cp + 4 * v) =
                    make_float4(lo[4 * v], lo[4 * v + 1], lo[4 * v + 2], lo[4 * v + 3]);
        }
        if (row0 + 1 < NN) {
            float* cp = C + (size_t)(row0 + 1) * NCOLS + tx * TN;
#pragma unroll
            for (int v = 0; v < TN / 4; ++v)
                *reinterpret_cast<float4*>(cp + 4 * v) =
                    make_float4(hi[4 * v], hi[4 * v + 1], hi[4 * v + 2], hi[4 * v + 3]);
        }
    }
}

// ---------------- edge scatter (mean folded in as 1/deg scale) ------------
// L1: one warp per edge, 128 floats, lane handles a float4.
__global__ __launch_bounds__(256)
void k_scatter1(const int* __restrict__ edges) {
    const int gw = (blockIdx.x * 256 + threadIdx.x) >> 5;
    if (gw >= RR * EE) return;
    const int r = gw / EE;
    const int e = gw - r * EE;
    const int* eb = edges + r * 2 * EE;
    const int src = eb[e];
    const int dst = eb[EE + e];
    const float wgt = g_dinv[r * NN + dst];
    const int l = threadIdx.x & 31;
    const float4 v = *reinterpret_cast<const float4*>(
        g_Wh1 + ((size_t)r * NN + src) * DH + l * 4);
    float* p = g_h + (size_t)dst * DH + l * 4;
    atomicAdd(p + 0, v.x * wgt);
    atomicAdd(p + 1, v.y * wgt);
    atomicAdd(p + 2, v.z * wgt);
    atomicAdd(p + 3, v.w * wgt);
}

// L2: 64 floats per edge -> two edges per warp (16 lanes each).
__global__ __launch_bounds__(256)
void k_scatter2(const int* __restrict__ edges, float* __restrict__ out) {
    const int gw = (blockIdx.x * 256 + threadIdx.x) >> 5;
    const int half = (threadIdx.x >> 4) & 1;
    const int eg = gw * 2 + half;
    if (eg >= RR * EE) return;
    const int r = eg / EE;
    const int e = eg - r * EE;
    const int* eb = edges + r * 2 * EE;
    const int src = eb[e];
    const int dst = eb[EE + e];
    const float wgt = g_dinv[r * NN + dst];
    const int l = threadIdx.x & 15;
    const float4 v = *reinterpret_cast<const float4*>(
        g_Wh2 + ((size_t)r * NN + src) * DOUT + l * 4);
    float* p = out + (size_t)dst * DOUT + l * 4;
    atomicAdd(p + 0, v.x * wgt);
    atomicAdd(p + 1, v.y * wgt);
    atomicAdd(p + 2, v.z * wgt);
    atomicAdd(p + 3, v.w * wgt);
}

// -------------------------------- launch ----------------------------------
extern "C" void kernel_launch(void* const* d_in, const int* in_sizes, int n_in,
                              void* d_out, int out_size) {
    const float* feat  = (const float*)d_in[0];
    const float* W1    = (const float*)d_in[1];
    const float* b1    = (const float*)d_in[2];
    const float* W2    = (const float*)d_in[3];
    const float* b2    = (const float*)d_in[4];
    const int*   edges = (const int*)d_in[5];
    float* out = (float*)d_out;

    // device addresses of scratch symbols (host-side API, not captured)
    void *pFeatT, *pHT, *pWh1, *pWh2, *pH;
    cudaGetSymbolAddress(&pFeatT, g_featT);
    cudaGetSymbolAddress(&pHT,    g_hT);
    cudaGetSymbolAddress(&pWh1,   g_Wh1);
    cudaGetSymbolAddress(&pWh2,   g_Wh2);
    cudaGetSymbolAddress(&pH,     g_h);

    const int smem1 = (128 * 128 + 128 * 2 * 128) * 4;  // 192 KB
    const int smem2 = (128 * 128 + 128 * 2 * 64) * 4;   // 128 KB
    cudaFuncSetAttribute(k_gemm<128, 7>, cudaFuncAttributeMaxDynamicSharedMemorySize, smem1);
    cudaFuncSetAttribute(k_gemm<64, 6>,  cudaFuncAttributeMaxDynamicSharedMemorySize, smem2);

    // degrees + bias-gated accumulator init
    k_zero_deg<<<(RR * NN + 255) / 256, 256>>>();
    k_count<<<(RR * EE + 255) / 256, 256>>>(edges);
    k_dinv<<<(RR * NN + 255) / 256, 256>>>();
    k_init_h<<<(NN * DH + 255) / 256, 256>>>(b1);
    k_init_out<<<(NN * DOUT + 255) / 256, 256>>>(b2, out);

    dim3 tb(32, 8);
    dim3 tg((NN + 31) / 32, 4);
    dim3 gg((NN + 127) / 128, 1, RR);

    // layer 1
    k_transpose<false><<<tg, tb>>>(feat, (float*)pFeatT);
    k_gemm<128, 7><<<gg, 256, smem1>>>((const float*)pFeatT, W1, (float*)pWh1);
    k_scatter1<<<(RR * EE * 32 + 255) / 256, 256>>>(edges);

    // layer 2 (relu fused into transpose)
    k_transpose<true><<<tg, tb>>>((const float*)pH, (float*)pHT);
    k_gemm<64, 6><<<gg, 256, smem2>>>((const float*)pHT, W2, (float*)pWh2);
    k_scatter2<<<(RR * EE * 16 + 255) / 256, 256>>>(edges, out);
}

// round 2
// speedup vs baseline: 1.3093x; 1.3093x over previous
#include <cuda_runtime.h>
#include <cstdint>
#include <cstddef>

// Problem constants
#define NN   50000
#define EE   200000
#define RR   4
#define DIN  128
#define DH   128
#define DOUT 64

#define SCAN_N (RR * NN)          // 200000
#define CHUNK  2048               // per scan block: 256 thr * 8
#define NBLK   ((SCAN_N + CHUNK - 1) / CHUNK)   // 98

// -------- scratch (static device globals; no runtime allocation) --------
__device__ float g_Wh1[RR * NN * DH];       // per-etype L1 GEMM out
__device__ float g_h[NN * DH];              // relu(layer-1 aggregate)
__device__ float g_Wh2[RR * NN * DOUT];     // per-etype L2 GEMM out
__device__ float g_featT[DIN * NN];         // feat transposed (k-major)
__device__ float g_hT[DH * NN];             // relu(h) transposed
__device__ int   g_deg[SCAN_N];
__device__ int   g_off[SCAN_N];             // CSR row offsets (exclusive scan of deg)
__device__ int   g_cur[SCAN_N];             // binning cursors
__device__ int   g_bsum[NBLK];              // scan block sums
__device__ int   g_esrc[RR * EE];           // CSR-sorted src ids

// -------- packed f32x2 FMA (ptxas never auto-emits FFMA2; 2x fp32 rate) ----
static __device__ __forceinline__ void fma2(unsigned long long& d,
                                            unsigned long long a,
                                            unsigned long long b) {
    asm("fma.rn.f32x2 %0, %1, %2, %0;" : "+l"(d) : "l"(a), "l"(b));
}

// ---------------- degree / CSR build ----------------
__global__ void k_zero() {
    int i = blockIdx.x * 256 + threadIdx.x;
    if (i < SCAN_N) { g_deg[i] = 0; g_cur[i] = 0; }
}

__global__ void k_count(const int* __restrict__ edges) {
    int i = blockIdx.x * 256 + threadIdx.x;
    if (i >= RR * EE) return;
    int r = i / EE;
    int e = i - r * EE;
    int dst = edges[r * 2 * EE + EE + e];
    atomicAdd(&g_deg[r * NN + dst], 1);
}

// exclusive scan of g_deg -> g_off, 3 kernels
__global__ __launch_bounds__(256) void k_scan1() {
    __shared__ int wsum[8];
    const int b = blockIdx.x, t = threadIdx.x;
    const int base = b * CHUNK + t * 8;
    int v[8]; int s = 0;
#pragma unroll
    for (int i = 0; i < 8; ++i) {
        int idx = base + i;
        int x = (idx < SCAN_N) ? g_deg[idx] : 0;
        v[i] = s; s += x;
    }
    const int lane = t & 31, w = t >> 5;
    int x = s;
#pragma unroll
    for (int o = 1; o < 32; o <<= 1) {
        int n = __shfl_up_sync(~0u, x, o);
        if (lane >= o) x += n;
    }
    if (lane == 31) wsum[w] = x;
    __syncthreads();
    if (t == 0) {
        int acc = 0;
#pragma unroll
        for (int i = 0; i < 8; ++i) { int tmp = wsum[i]; wsum[i] = acc; acc += tmp; }
        g_bsum[b] = acc;
    }
    __syncthreads();
    const int toff = wsum[w] + (x - s);
#pragma unroll
    for (int i = 0; i < 8; ++i) {
        int idx = base + i;
        if (idx < SCAN_N) g_off[idx] = toff + v[i];
    }
}

__global__ void k_scan2() {   // single block of 128, scans NBLK(<=128) sums
    __shared__ int ws[4];
    const int t = threadIdx.x;
    const int v = (t < NBLK) ? g_bsum[t] : 0;
    const int lane = t & 31, w = t >> 5;
    int x = v;
#pragma unroll
    for (int o = 1; o < 32; o <<= 1) {
        int n = __shfl_up_sync(~0u, x, o);
        if (lane >= o) x += n;
    }
    if (lane == 31) ws[w] = x;
    __syncthreads();
    if (t == 0) {
        int acc = 0;
#pragma unroll
        for (int i = 0; i < 4; ++i) { int tmp = ws[i]; ws[i] = acc; acc += tmp; }
    }
    __syncthreads();
    if (t < NBLK) g_bsum[t] = (x - v) + ws[w];
}

__global__ void k_scan3() {
    int i = blockIdx.x * 256 + threadIdx.x;
    if (i < SCAN_N) g_off[i] += g_bsum[i >> 11];
}

__global__ void k_bin(const int* __restrict__ edges) {
    int i = blockIdx.x * 256 + threadIdx.x;
    if (i >= RR * EE) return;
    int r = i / EE;
    int e = i - r * EE;
    const int* eb = edges + r * 2 * EE;
    int src = eb[e];
    int dst = eb[EE + e];
    int idx = r * NN + dst;
    int pos = g_off[idx] + atomicAdd(&g_cur[idx], 1);
    g_esrc[pos] = src;
}

// ---------------- transpose [NN][128] -> [128][NN] ----------------
__global__ void k_transpose(const float* __restrict__ in, float* __restrict__ out) {
    __shared__ float tile[32][33];
    const int n0 = blockIdx.x * 32;
    const int c0 = blockIdx.y * 32;
    const int tx = threadIdx.x, ty = threadIdx.y;
#pragma unroll
    for (int i = 0; i < 32; i += 8) {
        const int n = n0 + ty + i;
        float v = 0.f;
        if (n < NN) v = in[(size_t)n * 128 + c0 + tx];
        tile[ty + i][tx] = v;
    }
    __syncthreads();
    const int n = n0 + tx;
    if (n < NN) {
#pragma unroll
        for (int i = 0; i < 32; i += 8)
            out[(size_t)(c0 + ty + i) * NN + n] = tile[tx][ty + i];
    }
}

// ---------------- batched SGEMM: C[r] = A @ W[r] (no bias) ----------------
template <int NCOLS, int LOGN>
__global__ __launch_bounds__(256, 1)
void k_gemm(const float* __restrict__ AT,     // [128][NN] k-major
            const float* __restrict__ Wall,   // [RR][128][NCOLS]
            float* __restrict__ Call)         // [RR][NN][NCOLS]
{
    constexpr int TN = NCOLS / 16;
    extern __shared__ __align__(16) float smem[];
    float* As = smem;               // [128][128]  (k-major)
    float* Bs = smem + 128 * 128;   // [128][2*NCOLS] duplicated

    const int r  = blockIdx.z;
    const int m0 = blockIdx.x * 128;
    const float* W = Wall + r * 128 * NCOLS;
    float* C = Call + (size_t)r * NN * NCOLS;

    const int tid = threadIdx.x;
    {   // A tile
        const int w = tid >> 5, l = tid & 31;
        const int m = 4 * l;
        const int gm = m0 + m;
#pragma unroll
        for (int it = 0; it < 16; ++it) {
            const int k = w * 16 + it;
            float4 v = make_float4(0.f, 0.f, 0.f, 0.f);
            if (gm < NN) v = *reinterpret_cast<const float4*>(AT + (size_t)k * NN + gm);
            *reinterpret_cast<float4*>(As + k * 128 + m) = v;
        }
    }
    {   // W tile, duplicated
#pragma unroll
        for (int idx = tid; idx < 128 * NCOLS; idx += 256) {
            const int k = idx >> LOGN;
            const int n = idx & (NCOLS - 1);
            const float wv = W[idx];
            *reinterpret_cast<float2*>(Bs + k * 2 * NCOLS + 2 * n) = make_float2(wv, wv);
        }
    }
    __syncthreads();

    const int tx = tid & 15;
    const int ty = tid >> 4;

    unsigned long long acc[4][TN];
#pragma unroll
    for (int p = 0; p < 4; ++p)
#pragma unroll
        for (int j = 0; j < TN; ++j) acc[p][j] = 0ull;

#pragma unroll 8
    for (int k = 0; k < 128; ++k) {
        unsigned long long a[4], b[TN];
        ulonglong2 av0 = *reinterpret_cast<const ulonglong2*>(As + k * 128 + ty * 8);
        ulonglong2 av1 = *reinterpret_cast<const ulonglong2*>(As + k * 128 + ty * 8 + 4);
        a[0] = av0.x; a[1] = av0.y; a[2] = av1.x; a[3] = av1.y;
#pragma unroll
        for (int q = 0; q < TN / 2; ++q) {
            ulonglong2 bv = *reinterpret_cast<const ulonglong2*>(
                Bs + k * 2 * NCOLS + tx * 2 * TN + 4 * q);
            b[2 * q] = bv.x; b[2 * q + 1] = bv.y;
        }
#pragma unroll
        for (int p = 0; p < 4; ++p)
#pragma unroll
            for (int j = 0; j < TN; ++j)
                fma2(acc[p][j], a[p], b[j]);
    }

#pragma unroll
    for (int p = 0; p < 4; ++p) {
        float lo[TN], hi[TN];
#pragma unroll
        for (int j = 0; j < TN; ++j) {
            float2 t = *reinterpret_cast<float2*>(&acc[p][j]);
            lo[j] = t.x; hi[j] = t.y;
        }
        const int row0 = m0 + ty * 8 + 2 * p;
        if (row0 < NN) {
            float* cp = C + (size_t)row0 * NCOLS + tx * TN;
#pragma unroll
            for (int v = 0; v < TN / 4; ++v)
                *reinterpret_cast<float4*>(cp + 4 * v) =
                    make_float4(lo[4 * v], lo[4 * v + 1], lo[4 * v + 2], lo[4 * v + 3]);
        }
        if (row0 + 1 < NN) {
            float* cp = C + (size_t)(row0 + 1) * NCOLS + tx * TN;
#pragma unroll
            for (int v = 0; v < TN / 4; ++v)
                *reinterpret_cast<float4*>(cp + 4 * v) =
                    make_float4(hi[4 * v], hi[4 * v + 1], hi[4 * v + 2], hi[4 * v + 3]);
        }
    }
}

// ---------------- CSR gather-sum aggregators (no atomics) ------------------
// Layer 1: one warp per node; lane owns 4 channels (128 total).
// Folds 1/deg, bias gating, and ReLU. Writes g_h once.
__global__ __launch_bounds__(256)
void k_agg1(const float* __restrict__ b1) {
    const int gw = (blockIdx.x * 256 + threadIdx.x) >> 5;
    if (gw >= NN) return;
    const int lane = threadIdx.x & 31;
    float4 acc = make_float4(0.f, 0.f, 0.f, 0.f);
#pragma unroll
    for (int r = 0; r < RR; ++r) {
        const int idx = r * NN + gw;
        const int deg = g_deg[idx];
        if (deg == 0) continue;
        const int beg = g_off[idx];
        float4 s = make_float4(0.f, 0.f, 0.f, 0.f);
        for (int base = 0; base < deg; base += 32) {
            const int my = base + lane;
            const int src_l = (my < deg) ? g_esrc[beg + my] : 0;
            const int n = min(32, deg - base);
            for (int j = 0; j < n; ++j) {
                const int src = __shfl_sync(~0u, src_l, j);
                const float4 v = *reinterpret_cast<const float4*>(
                    g_Wh1 + ((size_t)r * NN + src) * DH + lane * 4);
                s.x += v.x; s.y += v.y; s.z += v.z; s.w += v.w;
            }
        }
        const float d = 1.0f / (float)deg;
        const float4 bb = *reinterpret_cast<const float4*>(b1 + r * DH + lane * 4);
        acc.x += s.x * d + bb.x;
        acc.y += s.y * d + bb.y;
        acc.z += s.z * d + bb.z;
        acc.w += s.w * d + bb.w;
    }
    acc.x = fmaxf(acc.x, 0.f);
    acc.y = fmaxf(acc.y, 0.f);
    acc.z = fmaxf(acc.z, 0.f);
    acc.w = fmaxf(acc.w, 0.f);
    *reinterpret_cast<float4*>(g_h + (size_t)gw * DH + lane * 4) = acc;
}

// Layer 2: one warp per node; lane owns 2 channels (64 total). Writes out.
__global__ __launch_bounds__(256)
void k_agg2(const float* __restrict__ b2, float* __restrict__ out) {
    const int gw = (blockIdx.x * 256 + threadIdx.x) >> 5;
    if (gw >= NN) return;
    const int lane = threadIdx.x & 31;
    float2 acc = make_float2(0.f, 0.f);
#pragma unroll
    for (int r = 0; r < RR; ++r) {
        const int idx = r * NN + gw;
        const int deg = g_deg[idx];
        if (deg == 0) continue;
        const int beg = g_off[idx];
        float2 s = make_float2(0.f, 0.f);
        for (int base = 0; base < deg; base += 32) {
            const int my = base + lane;
            const int src_l = (my < deg) ? g_esrc[beg + my] : 0;
            const int n = min(32, deg - base);
            for (int j = 0; j < n; ++j) {
                const int src = __shfl_sync(~0u, src_l, j);
                const float2 v = *reinterpret_cast<const float2*>(
                    g_Wh2 + ((size_t)r * NN + src) * DOUT + lane * 2);
                s.x += v.x; s.y += v.y;
            }
        }
        const float d = 1.0f / (float)deg;
        const float2 bb = *reinterpret_cast<const float2*>(b2 + r * DOUT + lane * 2);
        acc.x += s.x * d + bb.x;
        acc.y += s.y * d + bb.y;
    }
    *reinterpret_cast<float2*>(out + (size_t)gw * DOUT + lane * 2) = acc;
}

// -------------------------------- launch ----------------------------------
extern "C" void kernel_launch(void* const* d_in, const int* in_sizes, int n_in,
                              void* d_out, int out_size) {
    const float* feat  = (const float*)d_in[0];
    const float* W1    = (const float*)d_in[1];
    const float* b1    = (const float*)d_in[2];
    const float* W2    = (const float*)d_in[3];
    const float* b2    = (const float*)d_in[4];
    const int*   edges = (const int*)d_in[5];
    float* out = (float*)d_out;

    void *pFeatT, *pHT, *pWh1, *pWh2, *pH;
    cudaGetSymbolAddress(&pFeatT, g_featT);
    cudaGetSymbolAddress(&pHT,    g_hT);
    cudaGetSymbolAddress(&pWh1,   g_Wh1);
    cudaGetSymbolAddress(&pWh2,   g_Wh2);
    cudaGetSymbolAddress(&pH,     g_h);

    const int smem1 = (128 * 128 + 128 * 2 * 128) * 4;  // 192 KB
    const int smem2 = (128 * 128 + 128 * 2 * 64) * 4;   // 128 KB
    cudaFuncSetAttribute(k_gemm<128, 7>, cudaFuncAttributeMaxDynamicSharedMemorySize, smem1);
    cudaFuncSetAttribute(k_gemm<64, 6>,  cudaFuncAttributeMaxDynamicSharedMemorySize, smem2);

    dim3 tb(32, 8);
    dim3 tg((NN + 31) / 32, 4);
    dim3 gg((NN + 127) / 128, 1, RR);
    const int aggGrid = (NN * 32 + 255) / 256;

    // 1-3: degree count + feat transpose
    k_zero<<<(SCAN_N + 255) / 256, 256>>>();
    k_count<<<(RR * EE + 255) / 256, 256>>>(edges);
    k_transpose<<<tg, tb>>>(feat, (float*)pFeatT);

    // 4: GEMM1 (positioned 4th so ncu -s5 -c1 captures it)
    k_gemm<128, 7><<<gg, 256, smem1>>>((const float*)pFeatT, W1, (float*)pWh1);

    // 5-8: CSR build
    k_scan1<<<NBLK, 256>>>();
    k_scan2<<<1, 128>>>();
    k_scan3<<<(SCAN_N + 255) / 256, 256>>>();
    k_bin<<<(RR * EE + 255) / 256, 256>>>(edges);

    // 9: layer-1 aggregate (bias + mean + relu fused)
    k_agg1<<<aggGrid, 256>>>(b1);

    // 10-12: layer 2
    k_transpose<<<tg, tb>>>((const float*)pH, (float*)pHT);
    k_gemm<64, 6><<<gg, 256, smem2>>>((const float*)pHT, W2, (float*)pWh2);
    k_agg2<<<aggGrid, 256>>>(b2, out);
}

// round 3
// speedup vs baseline: 2.5165x; 1.9221x over previous
#include <cuda_runtime.h>
#include <cstdint>
#include <cstddef>

// Problem constants
#define NN   50000
#define EE   200000
#define RR   4
#define DIN  128
#define DH   128
#define DOUT 64

#define SCAN_N (RR * NN)          // 200000
#define CHUNK  2048               // per scan block: 256 thr * 8
#define NBLK   ((SCAN_N + CHUNK - 1) / CHUNK)   // 98

// -------- scratch (static device globals; no runtime allocation) --------
__device__ float g_Wh1[RR * NN * DH];       // per-etype L1 GEMM out
__device__ float g_h[NN * DH];              // relu(layer-1 aggregate)
__device__ float g_Wh2[RR * NN * DOUT];     // per-etype L2 GEMM out
__device__ float g_featT[DIN * NN];         // feat transposed (k-major)
__device__ float g_hT[DH * NN];             // relu(h) transposed
__device__ int   g_deg[SCAN_N];
__device__ int   g_off[SCAN_N];             // CSR row offsets
__device__ int   g_cur[SCAN_N];             // binning cursors
__device__ int   g_bsum[NBLK];              // scan block sums
__device__ int   g_esrc[RR * EE];           // CSR-sorted src ids

// -------- packed f32x2 helpers (ptxas never auto-emits these) --------------
static __device__ __forceinline__ void fma2(unsigned long long& d,
                                            unsigned long long a,
                                            unsigned long long b) {
    asm("fma.rn.f32x2 %0, %1, %2, %0;" : "+l"(d) : "l"(a), "l"(b));
}
static __device__ __forceinline__ unsigned long long dup2(float w) {
    unsigned long long r;
    asm("mov.b64 %0, {%1, %1};" : "=l"(r) : "f"(w));
    return r;
}

// ---------------- degree / CSR build ----------------
__global__ void k_zero() {
    int i = blockIdx.x * 256 + threadIdx.x;
    if (i < SCAN_N) { g_deg[i] = 0; g_cur[i] = 0; }
}

__global__ void k_count(const int* __restrict__ edges) {
    int i = blockIdx.x * 256 + threadIdx.x;
    if (i >= RR * EE) return;
    int r = i / EE;
    int e = i - r * EE;
    int dst = edges[r * 2 * EE + EE + e];
    atomicAdd(&g_deg[r * NN + dst], 1);
}

__global__ __launch_bounds__(256) void k_scan1() {
    __shared__ int wsum[8];
    const int b = blockIdx.x, t = threadIdx.x;
    const int base = b * CHUNK + t * 8;
    int v[8]; int s = 0;
#pragma unroll
    for (int i = 0; i < 8; ++i) {
        int idx = base + i;
        int x = (idx < SCAN_N) ? g_deg[idx] : 0;
        v[i] = s; s += x;
    }
    const int lane = t & 31, w = t >> 5;
    int x = s;
#pragma unroll
    for (int o = 1; o < 32; o <<= 1) {
        int n = __shfl_up_sync(~0u, x, o);
        if (lane >= o) x += n;
    }
    if (lane == 31) wsum[w] = x;
    __syncthreads();
    if (t == 0) {
        int acc = 0;
#pragma unroll
        for (int i = 0; i < 8; ++i) { int tmp = wsum[i]; wsum[i] = acc; acc += tmp; }
        g_bsum[b] = acc;
    }
    __syncthreads();
    const int toff = wsum[w] + (x - s);
#pragma unroll
    for (int i = 0; i < 8; ++i) {
        int idx = base + i;
        if (idx < SCAN_N) g_off[idx] = toff + v[i];
    }
}

__global__ void k_scan2() {
    __shared__ int ws[4];
    const int t = threadIdx.x;
    const int v = (t < NBLK) ? g_bsum[t] : 0;
    const int lane = t & 31, w = t >> 5;
    int x = v;
#pragma unroll
    for (int o = 1; o < 32; o <<= 1) {
        int n = __shfl_up_sync(~0u, x, o);
        if (lane >= o) x += n;
    }
    if (lane == 31) ws[w] = x;
    __syncthreads();
    if (t == 0) {
        int acc = 0;
#pragma unroll
        for (int i = 0; i < 4; ++i) { int tmp = ws[i]; ws[i] = acc; acc += tmp; }
    }
    __syncthreads();
    if (t < NBLK) g_bsum[t] = (x - v) + ws[w];
}

__global__ void k_scan3() {
    int i = blockIdx.x * 256 + threadIdx.x;
    if (i < SCAN_N) g_off[i] += g_bsum[i >> 11];
}

__global__ void k_bin(const int* __restrict__ edges) {
    int i = blockIdx.x * 256 + threadIdx.x;
    if (i >= RR * EE) return;
    int r = i / EE;
    int e = i - r * EE;
    const int* eb = edges + r * 2 * EE;
    int src = eb[e];
    int dst = eb[EE + e];
    int idx = r * NN + dst;
    int pos = g_off[idx] + atomicAdd(&g_cur[idx], 1);
    g_esrc[pos] = src;
}

// ---------------- transpose [NN][128] -> [128][NN] ----------------
__global__ void k_transpose(const float* __restrict__ in, float* __restrict__ out) {
    __shared__ float tile[32][33];
    const int n0 = blockIdx.x * 32;
    const int c0 = blockIdx.y * 32;
    const int tx = threadIdx.x, ty = threadIdx.y;
#pragma unroll
    for (int i = 0; i < 32; i += 8) {
        const int n = n0 + ty + i;
        float v = 0.f;
        if (n < NN) v = in[(size_t)n * 128 + c0 + tx];
        tile[ty + i][tx] = v;
    }
    __syncthreads();
    const int n = n0 + tx;
    if (n < NN) {
#pragma unroll
        for (int i = 0; i < 32; i += 8)
            out[(size_t)(c0 + ty + i) * NN + n] = tile[tx][ty + i];
    }
}

// ---------------- k-streamed SGEMM: C[r] = A @ W[r] ------------------------
// A k-major [128][NN]. Tile 128m x NB n, kt=64 streamed, 256 threads,
// 2 CTAs/SM. B loaded plain; {w,w} f32x2 operands built by register packs.
// Thread micro-tile: 8m x (4*TN4) n, n split in TN4/... two float4 groups
// (tx*4 and NB/2+tx*4 for TN=8; single group for TN=4) -> all LDS.128
// lane-consecutive, conflict-free.
template <int TN>   // 8 (layer1, NB=128) or 4 (layer2, NB=64)
__global__ __launch_bounds__(256, 2)
void k_gemm(const float* __restrict__ AT,     // [128][NN] k-major
            const float* __restrict__ Wall,   // [RR][128][NB]
            float* __restrict__ Call)         // [RR][NN][NB]
{
    constexpr int NB = TN * 16;
    constexpr int KT = 64;
    extern __shared__ __align__(16) float smem[];
    float* As = smem;             // [KT][128]
    float* Bs = smem + KT * 128;  // [KT][NB]

    const int tid = threadIdx.x;
    const int r   = blockIdx.y;
    const int m0  = blockIdx.x * 128;
    const float* W = Wall + r * 128 * NB;
    float* C = Call + (size_t)r * NN * NB;

    const int tx = tid & 15;
    const int ty = tid >> 4;

    unsigned long long acc[4][TN];
#pragma unroll
    for (int p = 0; p < 4; ++p)
#pragma unroll
        for (int j = 0; j < TN; ++j) acc[p][j] = 0ull;

    for (int kt = 0; kt < 128; kt += KT) {
        if (kt) __syncthreads();
        // A tile: KT x 128 floats = KT*32 float4, 256 threads
#pragma unroll
        for (int i = 0; i < KT / 8; ++i) {
            const int j = i * 256 + tid;
            const int kk = j >> 5;
            const int c4 = (j & 31) * 4;
            const int gm = m0 + c4;
            float4 v = make_float4(0.f, 0.f, 0.f, 0.f);
            if (gm < NN) v = *reinterpret_cast<const float4*>(
                AT + (size_t)(kt + kk) * NN + gm);
            *reinterpret_cast<float4*>(As + kk * 128 + c4) = v;
        }
        // B tile: KT x NB floats
#pragma unroll
        for (int i = 0; i < KT * NB / 4 / 256; ++i) {
            const int j = i * 256 + tid;
            const int kk = j / (NB / 4);
            const int c4 = (j % (NB / 4)) * 4;
            const float4 v = *reinterpret_cast<const float4*>(
                W + (size_t)(kt + kk) * NB + c4);
            *reinterpret_cast<float4*>(Bs + kk * NB + c4) = v;
        }
        __syncthreads();

#pragma unroll 4
        for (int k = 0; k < KT; ++k) {
            const ulonglong2 av0 = *reinterpret_cast<const ulonglong2*>(
                As + k * 128 + ty * 8);
            const ulonglong2 av1 = *reinterpret_cast<const ulonglong2*>(
                As + k * 128 + ty * 8 + 4);
            unsigned long long a[4] = {av0.x, av0.y, av1.x, av1.y};

            unsigned long long bd[TN];
            {
                const float4 b0 = *reinterpret_cast<const float4*>(
                    Bs + k * NB + tx * 4);
                bd[0] = dup2(b0.x); bd[1] = dup2(b0.y);
                bd[2] = dup2(b0.z); bd[3] = dup2(b0.w);
            }
            if (TN == 8) {
                const float4 b1 = *reinterpret_cast<const float4*>(
                    Bs + k * NB + NB / 2 + tx * 4);
                bd[4] = dup2(b1.x); bd[5] = dup2(b1.y);
                bd[6] = dup2(b1.z); bd[7] = dup2(b1.w);
            }
#pragma unroll
            for (int p = 0; p < 4; ++p)
#pragma unroll
                for (int j = 0; j < TN; ++j)
                    fma2(acc[p][j], a[p], bd[j]);
        }
    }

    // epilogue: acc[p][j] = {C[m0+ty*8+2p][n_j], C[...+1][n_j]}
#pragma unroll
    for (int p = 0; p < 4; ++p) {
        float lo[TN], hi[TN];
#pragma unroll
        for (int j = 0; j < TN; ++j) {
            float2 t = *reinterpret_cast<float2*>(&acc[p][j]);
            lo[j] = t.x; hi[j] = t.y;
        }
        const int row0 = m0 + ty * 8 + 2 * p;
        if (row0 < NN) {
            float* cp = C + (size_t)row0 * NB;
            *reinterpret_cast<float4*>(cp + tx * 4) =
                make_float4(lo[0], lo[1], lo[2], lo[3]);
            if (TN == 8)
                *reinterpret_cast<float4*>(cp + NB / 2 + tx * 4) =
                    make_float4(lo[4], lo[5], lo[6], lo[7]);
        }
        if (row0 + 1 < NN) {
            float* cp = C + (size_t)(row0 + 1) * NB;
            *reinterpret_cast<float4*>(cp + tx * 4) =
                make_float4(hi[0], hi[1], hi[2], hi[3]);
            if (TN == 8)
                *reinterpret_cast<float4*>(cp + NB / 2 + tx * 4) =
                    make_float4(hi[4], hi[5], hi[6], hi[7]);
        }
    }
}

// ---------------- CSR gather-sum aggregators (no atomics) ------------------
__global__ __launch_bounds__(256)
void k_agg1(const float* __restrict__ b1) {
    const int gw = (blockIdx.x * 256 + threadIdx.x) >> 5;
    if (gw >= NN) return;
    const int lane = threadIdx.x & 31;
    float4 acc = make_float4(0.f, 0.f, 0.f, 0.f);
#pragma unroll
    for (int r = 0; r < RR; ++r) {
        const int idx = r * NN + gw;
        const int deg = g_deg[idx];
        if (deg == 0) continue;
        const int beg = g_off[idx];
        float4 s = make_float4(0.f, 0.f, 0.f, 0.f);
        for (int base = 0; base < deg; base += 32) {
            const int my = base + lane;
            const int src_l = (my < deg) ? g_esrc[beg + my] : 0;
            const int n = min(32, deg - base);
            for (int j = 0; j < n; ++j) {
                const int src = __shfl_sync(~0u, src_l, j);
                const float4 v = *reinterpret_cast<const float4*>(
                    g_Wh1 + ((size_t)r * NN + src) * DH + lane * 4);
                s.x += v.x; s.y += v.y; s.z += v.z; s.w += v.w;
            }
        }
        const float d = 1.0f / (float)deg;
        const float4 bb = *reinterpret_cast<const float4*>(b1 + r * DH + lane * 4);
        acc.x += s.x * d + bb.x;
        acc.y += s.y * d + bb.y;
        acc.z += s.z * d + bb.z;
        acc.w += s.w * d + bb.w;
    }
    acc.x = fmaxf(acc.x, 0.f);
    acc.y = fmaxf(acc.y, 0.f);
    acc.z = fmaxf(acc.z, 0.f);
    acc.w = fmaxf(acc.w, 0.f);
    *reinterpret_cast<float4*>(g_h + (size_t)gw * DH + lane * 4) = acc;
}

__global__ __launch_bounds__(256)
void k_agg2(const float* __restrict__ b2, float* __restrict__ out) {
    const int gw = (blockIdx.x * 256 + threadIdx.x) >> 5;
    if (gw >= NN) return;
    const int lane = threadIdx.x & 31;
    float2 acc = make_float2(0.f, 0.f);
#pragma unroll
    for (int r = 0; r < RR; ++r) {
        const int idx = r * NN + gw;
        const int deg = g_deg[idx];
        if (deg == 0) continue;
        const int beg = g_off[idx];
        float2 s = make_float2(0.f, 0.f);
        for (int base = 0; base < deg; base += 32) {
            const int my = base + lane;
            const int src_l = (my < deg) ? g_esrc[beg + my] : 0;
            const int n = min(32, deg - base);
            for (int j = 0; j < n; ++j) {
                const int src = __shfl_sync(~0u, src_l, j);
                const float2 v = *reinterpret_cast<const float2*>(
                    g_Wh2 + ((size_t)r * NN + src) * DOUT + lane * 2);
                s.x += v.x; s.y += v.y;
            }
        }
        const float d = 1.0f / (float)deg;
        const float2 bb = *reinterpret_cast<const float2*>(b2 + r * DOUT + lane * 2);
        acc.x += s.x * d + bb.x;
        acc.y += s.y * d + bb.y;
    }
    *reinterpret_cast<float2*>(out + (size_t)gw * DOUT + lane * 2) = acc;
}

// -------------------------------- launch ----------------------------------
extern "C" void kernel_launch(void* const* d_in, const int* in_sizes, int n_in,
                              void* d_out, int out_size) {
    const float* feat  = (const float*)d_in[0];
    const float* W1    = (const float*)d_in[1];
    const float* b1    = (const float*)d_in[2];
    const float* W2    = (const float*)d_in[3];
    const float* b2    = (const float*)d_in[4];
    const int*   edges = (const int*)d_in[5];
    float* out = (float*)d_out;

    void *pFeatT, *pHT, *pWh1, *pWh2, *pH;
    cudaGetSymbolAddress(&pFeatT, g_featT);
    cudaGetSymbolAddress(&pHT,    g_hT);
    cudaGetSymbolAddress(&pWh1,   g_Wh1);
    cudaGetSymbolAddress(&pWh2,   g_Wh2);
    cudaGetSymbolAddress(&pH,     g_h);

    const int smem1 = (64 * 128 + 64 * 128) * 4;  // 64 KB
    const int smem2 = (64 * 128 + 64 * 64) * 4;   // 48 KB
    cudaFuncSetAttribute(k_gemm<8>, cudaFuncAttributeMaxDynamicSharedMemorySize, smem1);
    cudaFuncSetAttribute(k_gemm<4>, cudaFuncAttributeMaxDynamicSharedMemorySize, smem2);

    dim3 tb(32, 8);
    dim3 tg((NN + 31) / 32, 4);
    dim3 gg((NN + 127) / 128, RR);
    const int aggGrid = (NN * 32 + 255) / 256;

    // 1-3
    k_zero<<<(SCAN_N + 255) / 256, 256>>>();
    k_count<<<(RR * EE + 255) / 256, 256>>>(edges);
    k_transpose<<<tg, tb>>>(feat, (float*)pFeatT);

    // 4: GEMM1 (kept 4th so ncu captures it)
    k_gemm<8><<<gg, 256, smem1>>>((const float*)pFeatT, W1, (float*)pWh1);

    // 5-8: CSR build
    k_scan1<<<NBLK, 256>>>();
    k_scan2<<<1, 128>>>();
    k_scan3<<<(SCAN_N + 255) / 256, 256>>>();
    k_bin<<<(RR * EE + 255) / 256, 256>>>(edges);

    // 9: layer-1 aggregate
    k_agg1<<<aggGrid, 256>>>(b1);

    // 10-12: layer 2
    k_transpose<<<tg, tb>>>((const float*)pH, (float*)pHT);
    k_gemm<4><<<gg, 256, smem2>>>((const float*)pHT, W2, (float*)pWh2);
    k_agg2<<<aggGrid, 256>>>(b2, out);
}

// round 6
// speedup vs baseline: 3.4575x; 1.3740x over previous
#include <cuda_runtime.h>
#include <cuda_bf16.h>
#include <cstdint>
#include <cstddef>

// Problem constants
#define NN   50000
#define EE   200000
#define RR   4
#define DIN  128
#define DH   128
#define DOUT 64

#define SCAN_N (RR * NN)
#define CHUNK  2048
#define NBLK   ((SCAN_N + CHUNK - 1) / CHUNK)   // 98

// smem row stride for MMA tiles: 128 bf16 + 8 pad = 272 bytes (bank-rotating)
#define ROWB 272

// -------- scratch (static device globals) --------
__device__ float g_Wh1[RR * NN * DH];
__device__ float g_Wh2[RR * NN * DOUT];
__device__ __nv_bfloat16 g_featH[NN * DIN];
__device__ __nv_bfloat16 g_featL[NN * DIN];
__device__ __nv_bfloat16 g_hH[NN * DH];
__device__ __nv_bfloat16 g_hL[NN * DH];
__device__ __nv_bfloat16 g_w1H[RR * DH * DIN];    // [r][n][k]
__device__ __nv_bfloat16 g_w1L[RR * DH * DIN];
__device__ __nv_bfloat16 g_w2H[RR * DOUT * DH];   // [r][n][k]
__device__ __nv_bfloat16 g_w2L[RR * DOUT * DH];
__device__ int g_deg[SCAN_N];
__device__ int g_off[SCAN_N];
__device__ int g_cur[SCAN_N];
__device__ int g_bsum[NBLK];
__device__ int g_esrc[RR * EE];

__device__ __forceinline__ uint32_t smem_to_u32(const void* p) {
    uint32_t a;
    asm("{ .reg .u64 t; cvta.to.shared.u64 t, %1; cvt.u32.u64 %0, t; }"
        : "=r"(a) : "l"(p));
    return a;
}

#define LDSM_X4(r0, r1, r2, r3, addr) \
    asm volatile("ldmatrix.sync.aligned.m8n8.x4.shared.b16 {%0,%1,%2,%3}, [%4];" \
                 : "=r"(r0), "=r"(r1), "=r"(r2), "=r"(r3) : "r"(addr))

#define MMA_BF16(c, a, b0, b1) \
    asm volatile("mma.sync.aligned.m16n8k16.row.col.f32.bf16.bf16.f32 " \
                 "{%0,%1,%2,%3},{%4,%5,%6,%7},{%8,%9},{%0,%1,%2,%3};" \
                 : "+f"((c)[0]), "+f"((c)[1]), "+f"((c)[2]), "+f"((c)[3]) \
                 : "r"((a)[0]), "r"((a)[1]), "r"((a)[2]), "r"((a)[3]), \
                   "r"(b0), "r"(b1))

// -------- precision split --------
__device__ __forceinline__ void split_bf16(float v, __nv_bfloat16& h, __nv_bfloat16& l) {
    h = __float2bfloat16(v);
    l = __float2bfloat16(v - __bfloat162float(h));
}

// ==================== prep kernels ====================
__global__ void k_cvt_feat(const float* __restrict__ x) {
    int i = blockIdx.x * 256 + threadIdx.x;          // float4 index
    if (i >= NN * DIN / 4) return;
    float4 v = reinterpret_cast<const float4*>(x)[i];
    __nv_bfloat16 h0, l0, h1, l1, h2, l2, h3, l3;
    split_bf16(v.x, h0, l0); split_bf16(v.y, h1, l1);
    split_bf16(v.z, h2, l2); split_bf16(v.w, h3, l3);
    __nv_bfloat162 H0; H0.x = h0; H0.y = h1;
    __nv_bfloat162 H1; H1.x = h2; H1.y = h3;
    __nv_bfloat162 L0; L0.x = l0; L0.y = l1;
    __nv_bfloat162 L1; L1.x = l2; L1.y = l3;
    reinterpret_cast<__nv_bfloat162*>(g_featH)[2 * i]     = H0;
    reinterpret_cast<__nv_bfloat162*>(g_featH)[2 * i + 1] = H1;
    reinterpret_cast<__nv_bfloat162*>(g_featL)[2 * i]     = L0;
    reinterpret_cast<__nv_bfloat162*>(g_featL)[2 * i + 1] = L1;
}

__global__ void k_prep_w1(const float* __restrict__ W) {
    int i = blockIdx.x * 256 + threadIdx.x;
    if (i >= RR * 128 * 128) return;
    int r = i >> 14, kn = i & 16383, k = kn >> 7, n = kn & 127;
    float w = W[i];
    __nv_bfloat16 h, l; split_bf16(w, h, l);
    int o = r * 16384 + n * 128 + k;
    g_w1H[o] = h; g_w1L[o] = l;
}
__global__ void k_prep_w2(const float* __restrict__ W) {
    int i = blockIdx.x * 256 + threadIdx.x;
    if (i >= RR * 128 * 64) return;
    int r = i / (128 * 64), kn = i % (128 * 64), k = kn >> 6, n = kn & 63;
    float w = W[i];
    __nv_bfloat16 h, l; split_bf16(w, h, l);
    int o = r * 64 * 128 + n * 128 + k;
    g_w2H[o] = h; g_w2L[o] = l;
}

// ==================== degree / CSR build ====================
__global__ void k_zero() {
    int i = blockIdx.x * 256 + threadIdx.x;
    if (i < SCAN_N) { g_deg[i] = 0; g_cur[i] = 0; }
}
__global__ void k_count(const int* __restrict__ edges) {
    int i = blockIdx.x * 256 + threadIdx.x;
    if (i >= RR * EE) return;
    int r = i / EE, e = i - r * EE;
    int dst = edges[r * 2 * EE + EE + e];
    atomicAdd(&g_deg[r * NN + dst], 1);
}
__global__ __launch_bounds__(256) void k_scan1() {
    __shared__ int wsum[8];
    const int b = blockIdx.x, t = threadIdx.x;
    const int base = b * CHUNK + t * 8;
    int v[8]; int s = 0;
#pragma unroll
    for (int i = 0; i < 8; ++i) {
        int idx = base + i;
        int x = (idx < SCAN_N) ? g_deg[idx] : 0;
        v[i] = s; s += x;
    }
    const int lane = t & 31, w = t >> 5;
    int x = s;
#pragma unroll
    for (int o = 1; o < 32; o <<= 1) {
        int n = __shfl_up_sync(~0u, x, o);
        if (lane >= o) x += n;
    }
    if (lane == 31) wsum[w] = x;
    __syncthreads();
    if (t == 0) {
        int acc = 0;
#pragma unroll
        for (int i = 0; i < 8; ++i) { int tmp = wsum[i]; wsum[i] = acc; acc += tmp; }
        g_bsum[b] = acc;
    }
    __syncthreads();
    const int toff = wsum[w] + (x - s);
#pragma unroll
    for (int i = 0; i < 8; ++i) {
        int idx = base + i;
        if (idx < SCAN_N) g_off[idx] = toff + v[i];
    }
}
__global__ void k_scan2() {
    __shared__ int ws[4];
    const int t = threadIdx.x;
    const int v = (t < NBLK) ? g_bsum[t] : 0;
    const int lane = t & 31, w = t >> 5;
    int x = v;
#pragma unroll
    for (int o = 1; o < 32; o <<= 1) {
        int n = __shfl_up_sync(~0u, x, o);
        if (lane >= o) x += n;
    }
    if (lane == 31) ws[w] = x;
    __syncthreads();
    if (t == 0) {
        int acc = 0;
#pragma unroll
        for (int i = 0; i < 4; ++i) { int tmp = ws[i]; ws[i] = acc; acc += tmp; }
    }
    __syncthreads();
    if (t < NBLK) g_bsum[t] = (x - v) + ws[w];
}
__global__ void k_scan3() {
    int i = blockIdx.x * 256 + threadIdx.x;
    if (i < SCAN_N) g_off[i] += g_bsum[i >> 11];
}
__global__ void k_bin(const int* __restrict__ edges) {
    int i = blockIdx.x * 256 + threadIdx.x;
    if (i >= RR * EE) return;
    int r = i / EE, e = i - r * EE;
    const int* eb = edges + r * 2 * EE;
    int src = eb[e];
    int dst = eb[EE + e];
    int idx = r * NN + dst;
    int pos = g_off[idx] + atomicAdd(&g_cur[idx], 1);
    g_esrc[pos] = src;
}

// ==================== bf16x3 GEMM via mma.sync ====================
// C[r] = A @ W_r^T. A [M][128] row-major bf16 (hi/lo); B [NB][128] row-major
// (n rows, k cols) — non-trans ldmatrix of [n][k] tiles == .col B fragment.
// CTA: 128 thr = 4 warps, tile 64m x NB n, K=128 smem-resident.
// Warp grid 2m x 2n: warp = 32m x NB/2 n. NT = NB/32 jt-iterations of 16 n.
template <int ROWS>
__device__ __forceinline__ void load_tile(char* dst, const __nv_bfloat16* __restrict__ src,
                                          int valid_rows, int tid) {
#pragma unroll
    for (int i = 0; i < ROWS * 16 / 128; ++i) {
        const int j = i * 128 + tid;
        const int row = j >> 4;
        const int c16 = j & 15;
        uint4 v = make_uint4(0u, 0u, 0u, 0u);
        if (row < valid_rows)
            v = *reinterpret_cast<const uint4*>(src + (size_t)row * 128 + c16 * 8);
        *reinterpret_cast<uint4*>(dst + row * ROWB + c16 * 16) = v;
    }
}

template <int NB>   // 128 (layer1) or 64 (layer2)
__global__ __launch_bounds__(128)
void k_mma(const __nv_bfloat16* __restrict__ AH, const __nv_bfloat16* __restrict__ AL,
           const __nv_bfloat16* __restrict__ BH, const __nv_bfloat16* __restrict__ BL,
           float* __restrict__ C)
{
    constexpr int NT = NB / 32;     // 16-col jt steps per warp (warp n = NB/2)
    extern __shared__ __align__(16) char smem[];
    char* sAh = smem;
    char* sAl = sAh + 64 * ROWB;
    char* sBh = sAl + 64 * ROWB;
    char* sBl = sBh + NB * ROWB;

    const int tid  = threadIdx.x;
    const int lane = tid & 31;
    const int wid  = tid >> 5;
    const int m0   = blockIdx.x * 64;
    const int r    = blockIdx.y;
    const int valid = NN - m0;

    load_tile<64>(sAh, AH + (size_t)m0 * 128, valid < 64 ? valid : 64, tid);
    load_tile<64>(sAl, AL + (size_t)m0 * 128, valid < 64 ? valid : 64, tid);
    load_tile<NB>(sBh, BH + (size_t)r * NB * 128, NB, tid);
    load_tile<NB>(sBl, BL + (size_t)r * NB * 128, NB, tid);
    __syncthreads();

    const int wm = (wid >> 1) * 32;          // warp m offset in tile
    const int wn = (wid & 1) * (NB / 2);     // warp n offset

    // lane-dependent ldmatrix address components (bytes)
    const int aoff = (lane & 15) * ROWB + (lane >> 4) * 16;
    const int boff = ((lane & 7) + ((lane >> 4) << 3)) * ROWB + ((lane >> 3) & 1) * 16;

    const uint32_t uAh = smem_to_u32(sAh);
    const uint32_t uAl = smem_to_u32(sAl);
    const uint32_t uBh = smem_to_u32(sBh);
    const uint32_t uBl = smem_to_u32(sBl);

    float acc[2][NT * 2][4];
#pragma unroll
    for (int mt = 0; mt < 2; ++mt)
#pragma unroll
        for (int nt = 0; nt < NT * 2; ++nt)
#pragma unroll
            for (int q = 0; q < 4; ++q) acc[mt][nt][q] = 0.f;

#pragma unroll
    for (int ks = 0; ks < 8; ++ks) {
        const int kb = ks * 32;              // k16 step in bytes (16 bf16)
        uint32_t ah[2][4], al[2][4];
#pragma unroll
        for (int mt = 0; mt < 2; ++mt) {
            const uint32_t base = (wm + mt * 16) * ROWB + aoff + kb;
            LDSM_X4(ah[mt][0], ah[mt][1], ah[mt][2], ah[mt][3], uAh + base);
            LDSM_X4(al[mt][0], al[mt][1], al[mt][2], al[mt][3], uAl + base);
        }
#pragma unroll
        for (int jt = 0; jt < NT; ++jt) {    // pair of n8 tiles per iter
            const uint32_t bbase = (wn + jt * 16) * ROWB + boff + kb;
            uint32_t bh[4], bl[4];
            LDSM_X4(bh[0], bh[1], bh[2], bh[3], uBh + bbase);
            LDSM_X4(bl[0], bl[1], bl[2], bl[3], uBl + bbase);
#pragma unroll
            for (int mt = 0; mt < 2; ++mt) {
                MMA_BF16(acc[mt][2 * jt],     ah[mt], bh[0], bh[1]);
                MMA_BF16(acc[mt][2 * jt + 1], ah[mt], bh[2], bh[3]);
                MMA_BF16(acc[mt][2 * jt],     ah[mt], bl[0], bl[1]);
                MMA_BF16(acc[mt][2 * jt + 1], ah[mt], bl[2], bl[3]);
                MMA_BF16(acc[mt][2 * jt],     al[mt], bh[0], bh[1]);
                MMA_BF16(acc[mt][2 * jt + 1], al[mt], bh[2], bh[3]);
            }
        }
    }

    // epilogue: m16n8 frag: c0,c1 -> (row lane>>2, col (lane&3)*2), c2,c3 -> row+8
    float* Cr = C + (size_t)r * NN * NB;
#pragma unroll
    for (int mt = 0; mt < 2; ++mt) {
        const int row0 = m0 + wm + mt * 16 + (lane >> 2);
#pragma unroll
        for (int nt = 0; nt < NT * 2; ++nt) {
            const int col = wn + nt * 8 + (lane & 3) * 2;
            if (row0 < NN)
                *reinterpret_cast<float2*>(Cr + (size_t)row0 * NB + col) =
                    make_float2(acc[mt][nt][0], acc[mt][nt][1]);
            if (row0 + 8 < NN)
                *reinterpret_cast<float2*>(Cr + (size_t)(row0 + 8) * NB + col) =
                    make_float2(acc[mt][nt][2], acc[mt][nt][3]);
        }
    }
}

// ==================== CSR gather-sum aggregators ====================
__global__ __launch_bounds__(256)
void k_agg1(const float* __restrict__ b1) {
    const int gw = (blockIdx.x * 256 + threadIdx.x) >> 5;
    if (gw >= NN) return;
    const int lane = threadIdx.x & 31;
    float4 acc = make_float4(0.f, 0.f, 0.f, 0.f);
#pragma unroll
    for (int r = 0; r < RR; ++r) {
        const int idx = r * NN + gw;
        const int deg = g_deg[idx];
        if (deg == 0) continue;
        const int beg = g_off[idx];
        float4 s = make_float4(0.f, 0.f, 0.f, 0.f);
        for (int bse = 0; bse < deg; bse += 32) {
            const int my = bse + lane;
            const int src_l = (my < deg) ? g_esrc[beg + my] : 0;
            const int n = min(32, deg - bse);
            for (int j = 0; j < n; ++j) {
                const int src = __shfl_sync(~0u, src_l, j);
                const float4 v = *reinterpret_cast<const float4*>(
                    g_Wh1 + ((size_t)r * NN + src) * DH + lane * 4);
                s.x += v.x; s.y += v.y; s.z += v.z; s.w += v.w;
            }
        }
        const float d = 1.0f / (float)deg;
        const float4 bb = *reinterpret_cast<const float4*>(b1 + r * DH + lane * 4);
        acc.x += s.x * d + bb.x;
        acc.y += s.y * d + bb.y;
        acc.z += s.z * d + bb.z;
        acc.w += s.w * d + bb.w;
    }
    acc.x = fmaxf(acc.x, 0.f);
    acc.y = fmaxf(acc.y, 0.f);
    acc.z = fmaxf(acc.z, 0.f);
    acc.w = fmaxf(acc.w, 0.f);
    __nv_bfloat16 h0, l0, h1, l1, h2, l2, h3, l3;
    split_bf16(acc.x, h0, l0); split_bf16(acc.y, h1, l1);
    split_bf16(acc.z, h2, l2); split_bf16(acc.w, h3, l3);
    __nv_bfloat162 H0; H0.x = h0; H0.y = h1;
    __nv_bfloat162 H1; H1.x = h2; H1.y = h3;
    __nv_bfloat162 L0; L0.x = l0; L0.y = l1;
    __nv_bfloat162 L1; L1.x = l2; L1.y = l3;
    const size_t o2 = (size_t)gw * 64 + lane * 2;
    reinterpret_cast<__nv_bfloat162*>(g_hH)[o2]     = H0;
    reinterpret_cast<__nv_bfloat162*>(g_hH)[o2 + 1] = H1;
    reinterpret_cast<__nv_bfloat162*>(g_hL)[o2]     = L0;
    reinterpret_cast<__nv_bfloat162*>(g_hL)[o2 + 1] = L1;
}

__global__ __launch_bounds__(256)
void k_agg2(const float* __restrict__ b2, float* __restrict__ out) {
    const int gw = (blockIdx.x * 256 + threadIdx.x) >> 5;
    if (gw >= NN) return;
    const int lane = threadIdx.x & 31;
    float2 acc = make_float2(0.f, 0.f);
#pragma unroll
    for (int r = 0; r < RR; ++r) {
        const int idx = r * NN + gw;
        const int deg = g_deg[idx];
        if (deg == 0) continue;
        const int beg = g_off[idx];
        float2 s = make_float2(0.f, 0.f);
        for (int bse = 0; bse < deg; bse += 32) {
            const int my = bse + lane;
            const int src_l = (my < deg) ? g_esrc[beg + my] : 0;
            const int n = min(32, deg - bse);
            for (int j = 0; j < n; ++j) {
                const int src = __shfl_sync(~0u, src_l, j);
                const float2 v = *reinterpret_cast<const float2*>(
                    g_Wh2 + ((size_t)r * NN + src) * DOUT + lane * 2);
                s.x += v.x; s.y += v.y;
            }
        }
        const float d = 1.0f / (float)deg;
        const float2 bb = *reinterpret_cast<const float2*>(b2 + r * DOUT + lane * 2);
        acc.x += s.x * d + bb.x;
        acc.y += s.y * d + bb.y;
    }
    *reinterpret_cast<float2*>(out + (size_t)gw * DOUT + lane * 2) = acc;
}

// ==================== launch ====================
extern "C" void kernel_launch(void* const* d_in, const int* in_sizes, int n_in,
                              void* d_out, int out_size) {
    const float* feat  = (const float*)d_in[0];
    const float* W1    = (const float*)d_in[1];
    const float* b1    = (const float*)d_in[2];
    const float* W2    = (const float*)d_in[3];
    const float* b2    = (const float*)d_in[4];
    const int*   edges = (const int*)d_in[5];
    float* out = (float*)d_out;

    void *pFH, *pFL, *pHH, *pHL, *pW1H, *pW1L, *pW2H, *pW2L, *pWh1, *pWh2;
    cudaGetSymbolAddress(&pFH, g_featH);
    cudaGetSymbolAddress(&pFL, g_featL);
    cudaGetSymbolAddress(&pHH, g_hH);
    cudaGetSymbolAddress(&pHL, g_hL);
    cudaGetSymbolAddress(&pW1H, g_w1H);
    cudaGetSymbolAddress(&pW1L, g_w1L);
    cudaGetSymbolAddress(&pW2H, g_w2H);
    cudaGetSymbolAddress(&pW2L, g_w2L);
    cudaGetSymbolAddress(&pWh1, g_Wh1);
    cudaGetSymbolAddress(&pWh2, g_Wh2);

    const int smem1 = (64 + 64 + 128 + 128) * ROWB;  // 104448 B
    const int smem2 = (64 + 64 + 64 + 64) * ROWB;    //  69632 B
    cudaFuncSetAttribute(k_mma<128>, cudaFuncAttributeMaxDynamicSharedMemorySize, smem1);
    cudaFuncSetAttribute(k_mma<64>,  cudaFuncAttributeMaxDynamicSharedMemorySize, smem2);

    dim3 gg((NN + 63) / 64, RR);
    const int aggGrid = (NN * 32 + 255) / 256;

    // 1-3: conversions / weight prep
    k_cvt_feat<<<(NN * DIN / 4 + 255) / 256, 256>>>(feat);
    k_prep_w1<<<(RR * 128 * 128 + 255) / 256, 256>>>(W1);
    k_prep_w2<<<(RR * 128 * 64 + 255) / 256, 256>>>(W2);

    // 4: GEMM1 on tensor cores (kept 4th so ncu captures it)
    k_mma<128><<<gg, 128, smem1>>>((const __nv_bfloat16*)pFH, (const __nv_bfloat16*)pFL,
                                   (const __nv_bfloat16*)pW1H, (const __nv_bfloat16*)pW1L,
                                   (float*)pWh1);

    // 5-10: CSR build
    k_zero<<<(SCAN_N + 255) / 256, 256>>>();
    k_count<<<(RR * EE + 255) / 256, 256>>>(edges);
    k_scan1<<<NBLK, 256>>>();
    k_scan2<<<1, 128>>>();
    k_scan3<<<(SCAN_N + 255) / 256, 256>>>();
    k_bin<<<(RR * EE + 255) / 256, 256>>>(edges);

    // 11: layer-1 aggregate (mean + bias-gate + relu + bf16 split)
    k_agg1<<<aggGrid, 256>>>(b1);

    // 12: GEMM2 on tensor cores
    k_mma<64><<<gg, 128, smem2>>>((const __nv_bfloat16*)pHH, (const __nv_bfloat16*)pHL,
                                  (const __nv_bfloat16*)pW2H, (const __nv_bfloat16*)pW2L,
                                  (float*)pWh2);

    // 13: layer-2 aggregate -> out
    k_agg2<<<aggGrid, 256>>>(b2, out);
}